// round 14
// baseline (speedup 1.0000x reference)
#include <cuda_runtime.h>

#define N_ORB 256
#define NF    128
#define S     132          // padded row stride (floats); rows 16B-aligned
#define NB    8            // panel width
#define BATCH 4096
#define NTHREADS 256

// Panel: factor cols [kb,kb+NB) in warp-0 registers, physical swap of the
// panel slots at writeback via perm[]. Exports raw pivot rows to s_L11.
__device__ __forceinline__ void panel_factor(
    float* __restrict__ As, const int* __restrict__ rowoff,
    int* __restrict__ perm, int* __restrict__ s_prow,
    float* __restrict__ s_inv, float* __restrict__ s_L11,
    float* __restrict__ s_piv, int kb, int lane)
{
    float a[4][8];
    #pragma unroll
    for (int r = 0; r < 4; r++) {
        const int off = rowoff[4 * lane + r] + kb;
        *(float4*)&a[r][0] = *(const float4*)&As[off];
        *(float4*)&a[r][4] = *(const float4*)&As[off + 4];
    }
    #pragma unroll
    for (int m = 0; m < NB; m++) {
        const int k = kb + m;
        unsigned key = 0u;
        #pragma unroll
        for (int r = 0; r < 4; r++) {
            const int row = 4 * lane + r;
            if (row >= k) {
                unsigned kk = (__float_as_uint(fabsf(a[r][m])) & 0xFFFFFF80u)
                              | (unsigned)row;
                key = max(key, kk);
            }
        }
        key = __reduce_max_sync(0xffffffffu, key);
        const int p  = (int)(key & 127u);
        const int tk = k >> 2, lk = k & 3;
        const int tp = p >> 2, lp = p & 3;

        float rowk[8], rowp[8];
        #pragma unroll
        for (int j = 0; j < 8; j++) {
            float vk = a[0][j];
            if (lk == 1) vk = a[1][j];
            if (lk == 2) vk = a[2][j];
            if (lk == 3) vk = a[3][j];
            rowk[j] = __shfl_sync(0xffffffffu, vk, tk);
            float vp = a[0][j];
            if (lp == 1) vp = a[1][j];
            if (lp == 2) vp = a[2][j];
            if (lp == 3) vp = a[3][j];
            rowp[j] = __shfl_sync(0xffffffffu, vp, tp);
        }
        const float pivot = rowp[m];
        const float inv   = 1.0f / pivot;

        #pragma unroll
        for (int r = 0; r < 4; r++) {
            const bool isk = (lane == tk) && (r == lk);
            const bool isp = (lane == tp) && (r == lp);
            #pragma unroll
            for (int j = 0; j < 8; j++) {
                if (isk)      a[r][j] = rowp[j];
                else if (isp) a[r][j] = rowk[j];
            }
        }
        if (lane == 0) {
            s_inv[m] = inv;
            s_piv[k] = pivot;
            if (p != k) { int t0 = perm[k]; perm[k] = perm[p]; perm[p] = t0; }
        }
        if (lane < NB) s_L11[m * NB + lane] = rowp[lane];   // raw pivot row
        __syncwarp();

        float u[8];
        #pragma unroll
        for (int j = 0; j < 8; j++) u[j] = inv * rowp[j];
        #pragma unroll
        for (int r = 0; r < 4; r++) {
            const int row = 4 * lane + r;
            if (row > k) {
                const float mult = a[r][m];
                #pragma unroll
                for (int j = m + 1; j < 8; j++) a[r][j] -= mult * u[j];
            }
        }
    }
    #pragma unroll
    for (int r = 0; r < 4; r++) {
        const int off = perm[4 * lane + r] * S + kb;
        *(float4*)&As[off]     = *(float4*)&a[r][0];
        *(float4*)&As[off + 4] = *(float4*)&a[r][4];
    }
    if (lane < NB) s_prow[lane] = perm[kb + lane] * S;
    __syncwarp();
}

__global__ __launch_bounds__(NTHREADS, 3)
void slater_logdet_kernel(const int* __restrict__ n_occ,
                          const float* __restrict__ M,
                          float* __restrict__ out)
{
    extern __shared__ float As[];            // NF * S floats
    __shared__ int   Rsh[NF];
    __shared__ int   warpCnt[8];
    __shared__ int   perm[NF];
    __shared__ int   rowoff[NF];
    __shared__ int   s_prow[2][NB];
    __shared__ float s_inv[2][NB];
    __shared__ float s_L11[2][NB * NB];
    __shared__ float s_piv[NF];
    __shared__ float s_red[8];

    const int b    = blockIdx.x;
    const int tid  = threadIdx.x;
    const int lane = tid & 31;
    const int wid  = tid >> 5;

    // ---- Phase 1: occupied orbital indices, ascending ----
    int occ = (n_occ[b * N_ORB + tid] != 0);
    unsigned bm = __ballot_sync(0xffffffffu, occ);
    int rank = __popc(bm & ((1u << lane) - 1u));
    if (lane == 0) warpCnt[wid] = __popc(bm);
    if (tid < NF) { perm[tid] = tid; rowoff[tid] = tid * S; }
    __syncthreads();
    int base = 0;
    #pragma unroll
    for (int w = 0; w < 8; w++) if (w < wid) base += warpCnt[w];
    if (occ) Rsh[base + rank] = tid;
    __syncthreads();

    // ---- Phase 2: gather A[f][:] = M[R[f]][:] ----
    const float4* M4 = (const float4*)M;
    #pragma unroll
    for (int t = 0; t < 16; t++) {
        int idx = tid + t * NTHREADS;
        int f = idx >> 5;
        int q = idx & 31;
        float4 v = M4[Rsh[f] * 32 + q];
        *(float4*)&As[f * S + 4 * q] = v;
    }
    __syncthreads();

    // ---- Phase 3: blocked LU, lookahead, ONE block barrier per iteration ----
    if (wid == 0)
        panel_factor(As, rowoff, perm, s_prow[0], s_inv[0], s_L11[0],
                     s_piv, 0, lane);
    __syncthreads();

    for (int kb = 0; kb < NF - NB; kb += NB) {
        const int c0     = kb + NB;
        const int buf    = (kb >> 3) & 1;
        const int nrows  = NF - c0;
        const int ncols2 = nrows - NB;

        if (wid == 0) {
            // wait until warps 1..7 finish trsm + narrow for the next panel
            asm volatile("bar.sync 1, %0;" :: "n"(NTHREADS) : "memory");
            panel_factor(As, rowoff, perm, s_prow[buf ^ 1], s_inv[buf ^ 1],
                         s_L11[buf ^ 1], s_piv, c0, lane);
        } else {
            const int idx = tid - 32;        // 0 .. 223

            // (a) rowoff refresh (perm after panel kb)
            if (idx < NF) rowoff[idx] = perm[idx] * S;

            // (b) trsm of ALL trailing cols: V = diag(inv)*L11^{-1}*A12,
            //     in place; L11 hoisted from s_L11.
            if (idx < nrows) {
                const int j = c0 + idx;
                float rhs[NB];
                #pragma unroll
                for (int m = 0; m < NB; m++) rhs[m] = As[s_prow[buf][m] + j];
                float v[NB];
                #pragma unroll
                for (int m = 0; m < NB; m++) {
                    float l11m[NB];
                    *(float4*)&l11m[0] = *(const float4*)&s_L11[buf][m * NB];
                    *(float4*)&l11m[4] = *(const float4*)&s_L11[buf][m * NB + 4];
                    float acc = rhs[m];
                    #pragma unroll
                    for (int t2 = 0; t2 < m; t2++) acc -= l11m[t2] * v[t2];
                    v[m] = acc * s_inv[buf][m];
                }
                #pragma unroll
                for (int m = 0; m < NB; m++)
                    As[s_prow[buf][m] + j] = v[m];
            }

            // order trsm/rowoff writes before narrow reads (warps 1..7 only)
            asm volatile("bar.sync 2, 224;" ::: "memory");

            // (c) narrow next-panel update, (row, 4-col half) mapping
            for (int ii = idx; ii < 2 * nrows; ii += 224) {
                const int r  = c0 + (ii >> 1);
                const int j0 = c0 + 4 * (ii & 1);
                const int o  = rowoff[r];
                float l[NB];
                *(float4*)&l[0] = *(const float4*)&As[o + kb];
                *(float4*)&l[4] = *(const float4*)&As[o + kb + 4];
                float acc[4];
                *(float4*)acc = *(const float4*)&As[o + j0];
                #pragma unroll
                for (int m = 0; m < NB; m++) {
                    float u[4];
                    *(float4*)u = *(const float4*)&As[s_prow[buf][m] + j0];
                    #pragma unroll
                    for (int c = 0; c < 4; c++) acc[c] -= l[m] * u[c];
                }
                *(float4*)&As[o + j0] = *(float4*)acc;
            }

            // release warp 0 to factor the next panel
            asm volatile("bar.arrive 1, %0;" :: "n"(NTHREADS) : "memory");

            // (d) bulk GEMM: cols >= c0+8, rows via rowoff indirection
            if (ncols2 > 0) {
                const int nct = ncols2 >> 2;
                const int nrt = nrows  >> 2;
                if (lane < nct) {
                    const int j0 = c0 + NB + 4 * lane;
                    float uu[8][4];
                    #pragma unroll
                    for (int m = 0; m < NB; m++)
                        *(float4*)&uu[m][0] =
                            *(const float4*)&As[s_prow[buf][m] + j0];

                    for (int tr = wid - 1; tr < nrt; tr += 7) {
                        const int r0 = c0 + 4 * tr;
                        const int o0 = rowoff[r0],     o1 = rowoff[r0 + 1];
                        const int o2 = rowoff[r0 + 2], o3 = rowoff[r0 + 3];

                        float a0[4], a1[4], a2[4], a3[4];
                        *(float4*)a0 = *(const float4*)&As[o0 + j0];
                        *(float4*)a1 = *(const float4*)&As[o1 + j0];
                        *(float4*)a2 = *(const float4*)&As[o2 + j0];
                        *(float4*)a3 = *(const float4*)&As[o3 + j0];

                        #pragma unroll
                        for (int h = 0; h < 2; h++) {
                            float l0[4], l1[4], l2[4], l3[4];
                            *(float4*)l0 = *(const float4*)&As[o0 + kb + 4 * h];
                            *(float4*)l1 = *(const float4*)&As[o1 + kb + 4 * h];
                            *(float4*)l2 = *(const float4*)&As[o2 + kb + 4 * h];
                            *(float4*)l3 = *(const float4*)&As[o3 + kb + 4 * h];
                            #pragma unroll
                            for (int mm = 0; mm < 4; mm++) {
                                const int m = 4 * h + mm;
                                #pragma unroll
                                for (int c = 0; c < 4; c++) {
                                    a0[c] -= l0[mm] * uu[m][c];
                                    a1[c] -= l1[mm] * uu[m][c];
                                    a2[c] -= l2[mm] * uu[m][c];
                                    a3[c] -= l3[mm] * uu[m][c];
                                }
                            }
                        }
                        *(float4*)&As[o0 + j0] = *(float4*)a0;
                        *(float4*)&As[o1 + j0] = *(float4*)a1;
                        *(float4*)&As[o2 + j0] = *(float4*)a2;
                        *(float4*)&As[o3 + j0] = *(float4*)a3;
                    }
                }
            }
        }
        __syncthreads();
    }

    // ---- Phase 4: logabs = sum log|pivot| ----
    float lsum = 0.0f;
    if (tid < NF) lsum = logf(fabsf(s_piv[tid]));
    #pragma unroll
    for (int o = 16; o; o >>= 1) lsum += __shfl_down_sync(0xffffffffu, lsum, o);
    if (lane == 0) s_red[wid] = lsum;
    __syncthreads();
    if (tid == 0) {
        float tot = 0.0f;
        #pragma unroll
        for (int w = 0; w < 8; w++) tot += s_red[w];
        out[b] = tot;
    }
}

extern "C" void kernel_launch(void* const* d_in, const int* in_sizes, int n_in,
                              void* d_out, int out_size)
{
    (void)in_sizes; (void)n_in; (void)out_size;
    const int*   n_occ = (const int*)d_in[0];
    const float* M     = (const float*)d_in[1];
    float*       out   = (float*)d_out;

    const int smem = NF * S * (int)sizeof(float);   // 67584 bytes dynamic
    cudaFuncSetAttribute(slater_logdet_kernel,
                         cudaFuncAttributeMaxDynamicSharedMemorySize, smem);
    slater_logdet_kernel<<<BATCH, NTHREADS, smem>>>(n_occ, M, out);
}

// round 15
// speedup vs baseline: 1.0166x; 1.0166x over previous
#include <cuda_runtime.h>

#define N_ORB 256
#define NF    128
#define S     132          // padded row stride (floats); rows 16B-aligned
#define NB    8            // panel width
#define BATCH 4096
#define NTHREADS 256

// Panel: factor cols [kb,kb+NB) in one warp's registers, physical swap of the
// panel slots at writeback via perm[]. Exports raw pivot rows to s_L11.
__device__ __forceinline__ void panel_factor(
    float* __restrict__ As, const int* __restrict__ rowoff,
    int* __restrict__ perm, int* __restrict__ s_prow,
    float* __restrict__ s_inv, float* __restrict__ s_L11,
    float* __restrict__ s_piv, int kb, int lane)
{
    float a[4][8];
    #pragma unroll
    for (int r = 0; r < 4; r++) {
        const int off = rowoff[4 * lane + r] + kb;
        *(float4*)&a[r][0] = *(const float4*)&As[off];
        *(float4*)&a[r][4] = *(const float4*)&As[off + 4];
    }
    #pragma unroll
    for (int m = 0; m < NB; m++) {
        const int k = kb + m;
        unsigned key = 0u;
        #pragma unroll
        for (int r = 0; r < 4; r++) {
            const int row = 4 * lane + r;
            if (row >= k) {
                unsigned kk = (__float_as_uint(fabsf(a[r][m])) & 0xFFFFFF80u)
                              | (unsigned)row;
                key = max(key, kk);
            }
        }
        key = __reduce_max_sync(0xffffffffu, key);
        const int p  = (int)(key & 127u);
        const int tk = k >> 2, lk = k & 3;
        const int tp = p >> 2, lp = p & 3;

        float rowk[8], rowp[8];
        #pragma unroll
        for (int j = 0; j < 8; j++) {
            float vk = a[0][j];
            if (lk == 1) vk = a[1][j];
            if (lk == 2) vk = a[2][j];
            if (lk == 3) vk = a[3][j];
            rowk[j] = __shfl_sync(0xffffffffu, vk, tk);
            float vp = a[0][j];
            if (lp == 1) vp = a[1][j];
            if (lp == 2) vp = a[2][j];
            if (lp == 3) vp = a[3][j];
            rowp[j] = __shfl_sync(0xffffffffu, vp, tp);
        }
        const float pivot = rowp[m];
        const float inv   = 1.0f / pivot;

        #pragma unroll
        for (int r = 0; r < 4; r++) {
            const bool isk = (lane == tk) && (r == lk);
            const bool isp = (lane == tp) && (r == lp);
            #pragma unroll
            for (int j = 0; j < 8; j++) {
                if (isk)      a[r][j] = rowp[j];
                else if (isp) a[r][j] = rowk[j];
            }
        }
        if (lane == 0) {
            s_inv[m] = inv;
            s_piv[k] = pivot;
            if (p != k) { int t0 = perm[k]; perm[k] = perm[p]; perm[p] = t0; }
        }
        if (lane < NB) s_L11[m * NB + lane] = rowp[lane];   // raw pivot row
        __syncwarp();

        float u[8];
        #pragma unroll
        for (int j = 0; j < 8; j++) u[j] = inv * rowp[j];
        #pragma unroll
        for (int r = 0; r < 4; r++) {
            const int row = 4 * lane + r;
            if (row > k) {
                const float mult = a[r][m];
                #pragma unroll
                for (int j = m + 1; j < 8; j++) a[r][j] -= mult * u[j];
            }
        }
    }
    #pragma unroll
    for (int r = 0; r < 4; r++) {
        const int off = perm[4 * lane + r] * S + kb;
        *(float4*)&As[off]     = *(float4*)&a[r][0];
        *(float4*)&As[off + 4] = *(float4*)&a[r][4];
    }
    if (lane < NB) s_prow[lane] = perm[kb + lane] * S;
    __syncwarp();
}

__global__ __launch_bounds__(NTHREADS, 3)
void slater_logdet_kernel(const int* __restrict__ n_occ,
                          const float* __restrict__ M,
                          float* __restrict__ out)
{
    extern __shared__ float As[];            // NF * S floats
    __shared__ int   Rsh[NF];
    __shared__ int   warpCnt[8];
    __shared__ int   perm[NF];
    __shared__ int   rowoff[NF];
    __shared__ int   s_prow[2][NB];
    __shared__ float s_inv[2][NB];
    __shared__ float s_L11[2][NB * NB];
    __shared__ float s_piv[NF];
    __shared__ float s_red[8];

    const int b    = blockIdx.x;
    const int tid  = threadIdx.x;
    const int lane = tid & 31;
    const int wid  = tid >> 5;

    // ---- Phase 1: occupied orbital indices, ascending ----
    int occ = (n_occ[b * N_ORB + tid] != 0);
    unsigned bm = __ballot_sync(0xffffffffu, occ);
    int rank = __popc(bm & ((1u << lane) - 1u));
    if (lane == 0) warpCnt[wid] = __popc(bm);
    if (tid < NF) { perm[tid] = tid; rowoff[tid] = tid * S; }
    __syncthreads();
    int base = 0;
    #pragma unroll
    for (int w = 0; w < 8; w++) if (w < wid) base += warpCnt[w];
    if (occ) Rsh[base + rank] = tid;
    __syncthreads();

    // ---- Phase 2: gather A[f][:] = M[R[f]][:] ----
    const float4* M4 = (const float4*)M;
    #pragma unroll
    for (int t = 0; t < 16; t++) {
        int idx = tid + t * NTHREADS;
        int f = idx >> 5;
        int q = idx & 31;
        float4 v = M4[Rsh[f] * 32 + q];
        *(float4*)&As[f * S + 4 * q] = v;
    }
    __syncthreads();

    // ---- Phase 3: blocked LU with lookahead; rotating panel warp ----
    if (wid == 0)
        panel_factor(As, rowoff, perm, s_prow[0], s_inv[0], s_L11[0],
                     s_piv, 0, lane);
    __syncthreads();

    for (int kb = 0; kb < NF - NB; kb += NB) {
        const int c0     = kb + NB;
        const int it     = kb >> 3;          // iteration index 0..14
        const int buf    = it & 1;
        const int pw     = (it + 1) & 7;     // panel warp for the NEXT panel
        const int nrows  = NF - c0;
        const int ncols2 = nrows - NB;

        // step 1: rowoff refresh + trsm of ALL trailing cols (incl next panel)
        // V = diag(inv) * L11^{-1} * A12 in place; L11 hoisted from s_L11.
        if (tid < NF) rowoff[tid] = perm[tid] * S;
        if (tid < nrows) {
            const int j = c0 + tid;
            float rhs[NB];
            #pragma unroll
            for (int m = 0; m < NB; m++) rhs[m] = As[s_prow[buf][m] + j];
            float v[NB];
            #pragma unroll
            for (int m = 0; m < NB; m++) {
                float l11m[NB];
                *(float4*)&l11m[0] = *(const float4*)&s_L11[buf][m * NB];
                *(float4*)&l11m[4] = *(const float4*)&s_L11[buf][m * NB + 4];
                float acc = rhs[m];
                #pragma unroll
                for (int t2 = 0; t2 < m; t2++) acc -= l11m[t2] * v[t2];
                v[m] = acc * s_inv[buf][m];
            }
            #pragma unroll
            for (int m = 0; m < NB; m++)
                As[s_prow[buf][m] + j] = v[m];
        }
        __syncthreads();

        // step 2: ALL warps share the narrow next-panel update, mapped as
        // (row, 4-col half) across 2*nrows threads. Then the rotating panel
        // warp waits on named barrier 1 and factors the next panel; the
        // other 7 warps signal it and flow into the bulk GEMM.
        if (tid < 2 * nrows) {
            const int r  = c0 + (tid >> 1);
            const int j0 = c0 + 4 * (tid & 1);
            const int o  = rowoff[r];
            float l[NB];
            *(float4*)&l[0] = *(const float4*)&As[o + kb];
            *(float4*)&l[4] = *(const float4*)&As[o + kb + 4];
            float acc[4];
            *(float4*)acc = *(const float4*)&As[o + j0];
            #pragma unroll
            for (int m = 0; m < NB; m++) {
                float u[4];
                *(float4*)u = *(const float4*)&As[s_prow[buf][m] + j0];
                #pragma unroll
                for (int c = 0; c < 4; c++) acc[c] -= l[m] * u[c];
            }
            *(float4*)&As[o + j0] = *(float4*)acc;
        }

        if (wid == pw) {
            asm volatile("bar.sync 1, %0;" :: "n"(NTHREADS) : "memory");
            panel_factor(As, rowoff, perm, s_prow[buf ^ 1], s_inv[buf ^ 1],
                         s_L11[buf ^ 1], s_piv, c0, lane);
        } else {
            asm volatile("bar.arrive 1, %0;" :: "n"(NTHREADS) : "memory");

            // bulk GEMM: cols >= c0+8, rows via rowoff indirection
            if (ncols2 > 0) {
                const int wr  = (wid < pw) ? wid : (wid - 1);   // 0..6
                const int nct = ncols2 >> 2;
                const int nrt = nrows  >> 2;
                if (lane < nct) {
                    const int j0 = c0 + NB + 4 * lane;
                    float uu[8][4];
                    #pragma unroll
                    for (int m = 0; m < NB; m++)
                        *(float4*)&uu[m][0] =
                            *(const float4*)&As[s_prow[buf][m] + j0];

                    for (int tr = wr; tr < nrt; tr += 7) {
                        const int r0 = c0 + 4 * tr;
                        const int o0 = rowoff[r0],     o1 = rowoff[r0 + 1];
                        const int o2 = rowoff[r0 + 2], o3 = rowoff[r0 + 3];

                        float a0[4], a1[4], a2[4], a3[4];
                        *(float4*)a0 = *(const float4*)&As[o0 + j0];
                        *(float4*)a1 = *(const float4*)&As[o1 + j0];
                        *(float4*)a2 = *(const float4*)&As[o2 + j0];
                        *(float4*)a3 = *(const float4*)&As[o3 + j0];

                        #pragma unroll
                        for (int h = 0; h < 2; h++) {
                            float l0[4], l1[4], l2[4], l3[4];
                            *(float4*)l0 = *(const float4*)&As[o0 + kb + 4 * h];
                            *(float4*)l1 = *(const float4*)&As[o1 + kb + 4 * h];
                            *(float4*)l2 = *(const float4*)&As[o2 + kb + 4 * h];
                            *(float4*)l3 = *(const float4*)&As[o3 + kb + 4 * h];
                            #pragma unroll
                            for (int mm = 0; mm < 4; mm++) {
                                const int m = 4 * h + mm;
                                #pragma unroll
                                for (int c = 0; c < 4; c++) {
                                    a0[c] -= l0[mm] * uu[m][c];
                                    a1[c] -= l1[mm] * uu[m][c];
                                    a2[c] -= l2[mm] * uu[m][c];
                                    a3[c] -= l3[mm] * uu[m][c];
                                }
                            }
                        }
                        *(float4*)&As[o0 + j0] = *(float4*)a0;
                        *(float4*)&As[o1 + j0] = *(float4*)a1;
                        *(float4*)&As[o2 + j0] = *(float4*)a2;
                        *(float4*)&As[o3 + j0] = *(float4*)a3;
                    }
                }
            }
        }
        __syncthreads();
    }

    // ---- Phase 4: logabs = sum log|pivot| ----
    float lsum = 0.0f;
    if (tid < NF) lsum = logf(fabsf(s_piv[tid]));
    #pragma unroll
    for (int o = 16; o; o >>= 1) lsum += __shfl_down_sync(0xffffffffu, lsum, o);
    if (lane == 0) s_red[wid] = lsum;
    __syncthreads();
    if (tid == 0) {
        float tot = 0.0f;
        #pragma unroll
        for (int w = 0; w < 8; w++) tot += s_red[w];
        out[b] = tot;
    }
}

extern "C" void kernel_launch(void* const* d_in, const int* in_sizes, int n_in,
                              void* d_out, int out_size)
{
    (void)in_sizes; (void)n_in; (void)out_size;
    const int*   n_occ = (const int*)d_in[0];
    const float* M     = (const float*)d_in[1];
    float*       out   = (float*)d_out;

    const int smem = NF * S * (int)sizeof(float);   // 67584 bytes dynamic
    cudaFuncSetAttribute(slater_logdet_kernel,
                         cudaFuncAttributeMaxDynamicSharedMemorySize, smem);
    slater_logdet_kernel<<<BATCH, NTHREADS, smem>>>(n_occ, M, out);
}

// round 16
// speedup vs baseline: 1.0198x; 1.0032x over previous
#include <cuda_runtime.h>

#define N_ORB 256
#define NF    128
#define S     132          // padded row stride (floats); rows 16B-aligned
#define NB    8            // panel width
#define BATCH 4096
#define NTHREADS 256

// Panel: factor cols [kb,kb+NB) in one warp's registers, physical swap of the
// panel slots at writeback via perm[]. Exports raw pivot rows to s_L11.
__device__ __forceinline__ void panel_factor(
    float* __restrict__ As, const int* __restrict__ rowoff,
    int* __restrict__ perm, int* __restrict__ s_prow,
    float* __restrict__ s_inv, float* __restrict__ s_L11,
    float* __restrict__ s_piv, int kb, int lane)
{
    float a[4][8];
    #pragma unroll
    for (int r = 0; r < 4; r++) {
        const int off = rowoff[4 * lane + r] + kb;
        *(float4*)&a[r][0] = *(const float4*)&As[off];
        *(float4*)&a[r][4] = *(const float4*)&As[off + 4];
    }
    #pragma unroll
    for (int m = 0; m < NB; m++) {
        const int k = kb + m;
        unsigned key = 0u;
        #pragma unroll
        for (int r = 0; r < 4; r++) {
            const int row = 4 * lane + r;
            if (row >= k) {
                unsigned kk = (__float_as_uint(fabsf(a[r][m])) & 0xFFFFFF80u)
                              | (unsigned)row;
                key = max(key, kk);
            }
        }
        key = __reduce_max_sync(0xffffffffu, key);
        const int p  = (int)(key & 127u);
        const int tk = k >> 2, lk = k & 3;
        const int tp = p >> 2, lp = p & 3;

        float rowk[8], rowp[8];
        #pragma unroll
        for (int j = 0; j < 8; j++) {
            float vk = a[0][j];
            if (lk == 1) vk = a[1][j];
            if (lk == 2) vk = a[2][j];
            if (lk == 3) vk = a[3][j];
            rowk[j] = __shfl_sync(0xffffffffu, vk, tk);
            float vp = a[0][j];
            if (lp == 1) vp = a[1][j];
            if (lp == 2) vp = a[2][j];
            if (lp == 3) vp = a[3][j];
            rowp[j] = __shfl_sync(0xffffffffu, vp, tp);
        }
        const float pivot = rowp[m];
        const float inv   = 1.0f / pivot;

        #pragma unroll
        for (int r = 0; r < 4; r++) {
            const bool isk = (lane == tk) && (r == lk);
            const bool isp = (lane == tp) && (r == lp);
            #pragma unroll
            for (int j = 0; j < 8; j++) {
                if (isk)      a[r][j] = rowp[j];
                else if (isp) a[r][j] = rowk[j];
            }
        }
        if (lane == 0) {
            s_inv[m] = inv;
            s_piv[k] = pivot;
            if (p != k) { int t0 = perm[k]; perm[k] = perm[p]; perm[p] = t0; }
        }
        if (lane < NB) s_L11[m * NB + lane] = rowp[lane];   // raw pivot row
        __syncwarp();

        float u[8];
        #pragma unroll
        for (int j = 0; j < 8; j++) u[j] = inv * rowp[j];
        #pragma unroll
        for (int r = 0; r < 4; r++) {
            const int row = 4 * lane + r;
            if (row > k) {
                const float mult = a[r][m];
                #pragma unroll
                for (int j = m + 1; j < 8; j++) a[r][j] -= mult * u[j];
            }
        }
    }
    #pragma unroll
    for (int r = 0; r < 4; r++) {
        const int off = perm[4 * lane + r] * S + kb;
        *(float4*)&As[off]     = *(float4*)&a[r][0];
        *(float4*)&As[off + 4] = *(float4*)&a[r][4];
    }
    if (lane < NB) s_prow[lane] = perm[kb + lane] * S;
    __syncwarp();
}

__global__ __launch_bounds__(NTHREADS, 3)
void slater_logdet_kernel(const int* __restrict__ n_occ,
                          const float* __restrict__ M,
                          float* __restrict__ out)
{
    extern __shared__ float As[];            // NF * S floats
    __shared__ int   Rsh[NF];
    __shared__ int   warpCnt[8];
    __shared__ int   perm[NF];
    __shared__ int   rowoff[NF];
    __shared__ int   s_prow[2][NB];
    __shared__ float s_inv[2][NB];
    __shared__ float s_L11[2][NB * NB];
    __shared__ float s_V[NB * NF];           // dense V buffer (U12 of panel kb)
    __shared__ float s_piv[NF];
    __shared__ float s_red[8];

    const int b    = blockIdx.x;
    const int tid  = threadIdx.x;
    const int lane = tid & 31;
    const int wid  = tid >> 5;

    // ---- Phase 1: occupied orbital indices, ascending ----
    int occ = (n_occ[b * N_ORB + tid] != 0);
    unsigned bm = __ballot_sync(0xffffffffu, occ);
    int rank = __popc(bm & ((1u << lane) - 1u));
    if (lane == 0) warpCnt[wid] = __popc(bm);
    if (tid < NF) { perm[tid] = tid; rowoff[tid] = tid * S; }
    __syncthreads();
    int base = 0;
    #pragma unroll
    for (int w = 0; w < 8; w++) if (w < wid) base += warpCnt[w];
    if (occ) Rsh[base + rank] = tid;
    __syncthreads();

    // ---- Phase 2: gather A[f][:] = M[R[f]][:] ----
    const float4* M4 = (const float4*)M;
    #pragma unroll
    for (int t = 0; t < 16; t++) {
        int idx = tid + t * NTHREADS;
        int f = idx >> 5;
        int q = idx & 31;
        float4 v = M4[Rsh[f] * 32 + q];
        *(float4*)&As[f * S + 4 * q] = v;
    }
    __syncthreads();

    // ---- Phase 3: blocked LU with lookahead; rotating panel warp ----
    if (wid == 0)
        panel_factor(As, rowoff, perm, s_prow[0], s_inv[0], s_L11[0],
                     s_piv, 0, lane);
    __syncthreads();

    for (int kb = 0; kb < NF - NB; kb += NB) {
        const int c0     = kb + NB;
        const int it     = kb >> 3;          // iteration index 0..14
        const int buf    = it & 1;
        const int pw     = (it + 1) & 7;     // panel warp for the NEXT panel
        const int nrows  = NF - c0;
        const int ncols2 = nrows - NB;

        // step 1: rowoff refresh + trsm of ALL trailing cols.
        // V = diag(inv) * L11^{-1} * A12 written to DENSE s_V (U12 in As is
        // dead data; nothing downstream reads it from the matrix).
        if (tid < NF) rowoff[tid] = perm[tid] * S;
        if (tid < nrows) {
            const int j = c0 + tid;
            float rhs[NB];
            #pragma unroll
            for (int m = 0; m < NB; m++) rhs[m] = As[s_prow[buf][m] + j];
            float v[NB];
            #pragma unroll
            for (int m = 0; m < NB; m++) {
                float l11m[NB];
                *(float4*)&l11m[0] = *(const float4*)&s_L11[buf][m * NB];
                *(float4*)&l11m[4] = *(const float4*)&s_L11[buf][m * NB + 4];
                float acc = rhs[m];
                #pragma unroll
                for (int t2 = 0; t2 < m; t2++) acc -= l11m[t2] * v[t2];
                v[m] = acc * s_inv[buf][m];
            }
            #pragma unroll
            for (int m = 0; m < NB; m++)
                s_V[m * NF + tid] = v[m];
        }
        __syncthreads();

        // step 2: ALL warps share the narrow next-panel update, mapped as
        // (row, 4-col half) across 2*nrows threads; U read from dense s_V.
        // Then the rotating panel warp waits on named barrier 1 and factors
        // the next panel; the other 7 warps signal it and run the bulk GEMM.
        if (tid < 2 * nrows) {
            const int r  = c0 + (tid >> 1);
            const int jr = 4 * (tid & 1);            // 0 or 4 (col - c0)
            const int o  = rowoff[r];
            float l[NB];
            *(float4*)&l[0] = *(const float4*)&As[o + kb];
            *(float4*)&l[4] = *(const float4*)&As[o + kb + 4];
            float acc[4];
            *(float4*)acc = *(const float4*)&As[o + c0 + jr];
            #pragma unroll
            for (int m = 0; m < NB; m++) {
                float u[4];
                *(float4*)u = *(const float4*)&s_V[m * NF + jr];
                #pragma unroll
                for (int c = 0; c < 4; c++) acc[c] -= l[m] * u[c];
            }
            *(float4*)&As[o + c0 + jr] = *(float4*)acc;
        }

        if (wid == pw) {
            asm volatile("bar.sync 1, %0;" :: "n"(NTHREADS) : "memory");
            panel_factor(As, rowoff, perm, s_prow[buf ^ 1], s_inv[buf ^ 1],
                         s_L11[buf ^ 1], s_piv, c0, lane);
        } else {
            asm volatile("bar.arrive 1, %0;" :: "n"(NTHREADS) : "memory");

            // bulk GEMM: cols >= c0+8, U hoisted from dense s_V (no
            // indirection), rows via rowoff indirection.
            if (ncols2 > 0) {
                const int wr  = (wid < pw) ? wid : (wid - 1);   // 0..6
                const int nct = ncols2 >> 2;
                const int nrt = nrows  >> 2;
                if (lane < nct) {
                    const int jr = NB + 4 * lane;               // col - c0
                    const int j0 = c0 + jr;
                    float uu[8][4];
                    #pragma unroll
                    for (int m = 0; m < NB; m++)
                        *(float4*)&uu[m][0] = *(const float4*)&s_V[m * NF + jr];

                    for (int tr = wr; tr < nrt; tr += 7) {
                        const int r0 = c0 + 4 * tr;
                        const int o0 = rowoff[r0],     o1 = rowoff[r0 + 1];
                        const int o2 = rowoff[r0 + 2], o3 = rowoff[r0 + 3];

                        float a0[4], a1[4], a2[4], a3[4];
                        *(float4*)a0 = *(const float4*)&As[o0 + j0];
                        *(float4*)a1 = *(const float4*)&As[o1 + j0];
                        *(float4*)a2 = *(const float4*)&As[o2 + j0];
                        *(float4*)a3 = *(const float4*)&As[o3 + j0];

                        #pragma unroll
                        for (int h = 0; h < 2; h++) {
                            float l0[4], l1[4], l2[4], l3[4];
                            *(float4*)l0 = *(const float4*)&As[o0 + kb + 4 * h];
                            *(float4*)l1 = *(const float4*)&As[o1 + kb + 4 * h];
                            *(float4*)l2 = *(const float4*)&As[o2 + kb + 4 * h];
                            *(float4*)l3 = *(const float4*)&As[o3 + kb + 4 * h];
                            #pragma unroll
                            for (int mm = 0; mm < 4; mm++) {
                                const int m = 4 * h + mm;
                                #pragma unroll
                                for (int c = 0; c < 4; c++) {
                                    a0[c] -= l0[mm] * uu[m][c];
                                    a1[c] -= l1[mm] * uu[m][c];
                                    a2[c] -= l2[mm] * uu[m][c];
                                    a3[c] -= l3[mm] * uu[m][c];
                                }
                            }
                        }
                        *(float4*)&As[o0 + j0] = *(float4*)a0;
                        *(float4*)&As[o1 + j0] = *(float4*)a1;
                        *(float4*)&As[o2 + j0] = *(float4*)a2;
                        *(float4*)&As[o3 + j0] = *(float4*)a3;
                    }
                }
            }
        }
        __syncthreads();
    }

    // ---- Phase 4: logabs = sum log|pivot| ----
    float lsum = 0.0f;
    if (tid < NF) lsum = logf(fabsf(s_piv[tid]));
    #pragma unroll
    for (int o = 16; o; o >>= 1) lsum += __shfl_down_sync(0xffffffffu, lsum, o);
    if (lane == 0) s_red[wid] = lsum;
    __syncthreads();
    if (tid == 0) {
        float tot = 0.0f;
        #pragma unroll
        for (int w = 0; w < 8; w++) tot += s_red[w];
        out[b] = tot;
    }
}

extern "C" void kernel_launch(void* const* d_in, const int* in_sizes, int n_in,
                              void* d_out, int out_size)
{
    (void)in_sizes; (void)n_in; (void)out_size;
    const int*   n_occ = (const int*)d_in[0];
    const float* M     = (const float*)d_in[1];
    float*       out   = (float*)d_out;

    const int smem = NF * S * (int)sizeof(float);   // 67584 bytes dynamic
    cudaFuncSetAttribute(slater_logdet_kernel,
                         cudaFuncAttributeMaxDynamicSharedMemorySize, smem);
    slater_logdet_kernel<<<BATCH, NTHREADS, smem>>>(n_occ, M, out);
}